// round 6
// baseline (speedup 1.0000x reference)
#include <cuda_runtime.h>
#include <math.h>

#define NB 8
#define C 192
#define C3 576
#define NH 4
#define CH 48
#define HH 128
#define WW 128
#define HW 16384
#define SPLIT 32
#define PART_STRIDE (CH*CH + 2*CH)   /* 2400 */

// Scratch (device globals: no allocation allowed in kernel_launch)
__device__ float g_qkv [NB*C3*HW];                 // 302 MB: 1x1 conv output
__device__ float g_v   [NB*C*HW];                  // 100 MB: depthwise(v)
__device__ float g_part[SPLIT*NB*NH*PART_STRIDE];  // split-K partials
__device__ float g_score[NB*NH*CH*CH];             // softmaxed scores
__device__ float g_P   [NB*C*C];                   // fused W_proj @ blockdiag(score)

// ===========================================================================
// Tensor-core TF32 GEMM: C[z] = A[z] * B[z]
// A [M,K=192] row-major (astride per batch; 0 = shared), B row-major
// (bstride per batch), C [M,N]. BM=64, BN=128, BK=32, 256 threads,
// warp tile 32x32, double-buffered smem (48KB exactly).
// ===========================================================================
#define GBM 64
#define GBN 128
#define GBK 32
#define KD  192
#define GNT (KD/GBK)   /* 6 */

__device__ __forceinline__ unsigned f2tf(float f) {
    unsigned u; asm("cvt.rna.tf32.f32 %0, %1;" : "=r"(u) : "f"(f)); return u;
}

#define MMA_TF32(d, av, bv)                                                   \
  asm("mma.sync.aligned.m16n8k8.row.col.f32.tf32.tf32.f32 "                   \
      "{%0,%1,%2,%3}, {%4,%5,%6,%7}, {%8,%9}, {%0,%1,%2,%3};"                 \
      : "+f"(d[0]), "+f"(d[1]), "+f"(d[2]), "+f"(d[3])                        \
      : "r"(av[0]), "r"(av[1]), "r"(av[2]), "r"(av[3]),                       \
        "r"(bv[0]), "r"(bv[1]))

__global__ __launch_bounds__(256) void gemm_tf32_kernel(
    const float* __restrict__ A, const float* __restrict__ Bm, float* __restrict__ Cm,
    int M, int N, size_t astride, size_t bstride)
{
    __shared__ unsigned As[2][GBM * GBK];    // [m][k^((m&7)*4)], stride 32
    __shared__ unsigned Bs[2][GBK * GBN];    // [k][n], XOR-8 swizzled on n

    const int tid  = threadIdx.x;
    const int lane = tid & 31, wid = tid >> 5;
    const int wm = wid & 1, wn = wid >> 1;       // 2 x 4 warps
    const int g = lane >> 2, tig = lane & 3;

    const int m0 = blockIdx.y * GBM, n0 = blockIdx.x * GBN;
    const float* Ab = A + astride * blockIdx.z + (size_t)m0 * KD;
    const float* Bb = Bm + bstride * blockIdx.z + n0;
    float*       Cb = Cm + (size_t)blockIdx.z * M * N;

    float acc[2][4][4];
#pragma unroll
    for (int mi = 0; mi < 2; mi++)
#pragma unroll
        for (int ni = 0; ni < 4; ni++)
#pragma unroll
            for (int j = 0; j < 4; j++) acc[mi][ni][j] = 0.f;

    float4 areg[2];
    float4 breg[4];

    // prologue: LDG tile 0 + STS into buffer 0
#pragma unroll
    for (int i = 0; i < 2; i++) {
        int idx = tid * 2 + i, row = idx >> 3, kc = (idx & 7) * 4;
        areg[i] = *(const float4*)&Ab[(size_t)row * KD + kc];
    }
#pragma unroll
    for (int i = 0; i < 4; i++) {
        int idx = tid + i * 256, row = idx >> 5, c4 = idx & 31;
        breg[i] = *(const float4*)&Bb[(size_t)row * N + c4 * 4];
    }
#pragma unroll
    for (int i = 0; i < 2; i++) {
        int idx = tid * 2 + i, row = idx >> 3, kc = (idx & 7) * 4;
        int col = kc ^ ((row & 7) * 4);
        uint4 v = make_uint4(f2tf(areg[i].x), f2tf(areg[i].y), f2tf(areg[i].z), f2tf(areg[i].w));
        *(uint4*)&As[0][row * GBK + col] = v;
    }
#pragma unroll
    for (int i = 0; i < 4; i++) {
        int idx = tid + i * 256, row = idx >> 5, c4 = idx & 31;
        int col = (c4 * 4) ^ ((row & 3) * 8);
        uint4 v = make_uint4(f2tf(breg[i].x), f2tf(breg[i].y), f2tf(breg[i].z), f2tf(breg[i].w));
        *(uint4*)&Bs[0][row * GBN + col] = v;
    }
    __syncthreads();

#pragma unroll
    for (int t = 0; t < GNT; t++) {
        const int cur = t & 1;
        if (t + 1 < GNT) {
            int kofs = (t + 1) * GBK;
#pragma unroll
            for (int i = 0; i < 4; i++) {
                int idx = tid + i * 256, row = idx >> 5, c4 = idx & 31;
                breg[i] = *(const float4*)&Bb[(size_t)(kofs + row) * N + c4 * 4];
            }
#pragma unroll
            for (int i = 0; i < 2; i++) {
                int idx = tid * 2 + i, row = idx >> 3, kc = (idx & 7) * 4;
                areg[i] = *(const float4*)&Ab[(size_t)row * KD + kofs + kc];
            }
        }

#pragma unroll
        for (int kk = 0; kk < 4; kk++) {
            unsigned a[2][4], b[4][2];
            const int asw = g * 4;
            const int col0 = (kk * 8 + tig) ^ asw;
            const int col1 = (kk * 8 + 4 + tig) ^ asw;
#pragma unroll
            for (int mi = 0; mi < 2; mi++) {
                int r0 = (wm * 32 + mi * 16 + g) * GBK;
                int r1 = r0 + 8 * GBK;
                a[mi][0] = As[cur][r0 + col0];
                a[mi][1] = As[cur][r1 + col0];
                a[mi][2] = As[cur][r0 + col1];
                a[mi][3] = As[cur][r1 + col1];
            }
            const unsigned* Bp0 = Bs[cur] + (kk * 8 + tig) * GBN;
            const unsigned* Bp1 = Bs[cur] + (kk * 8 + tig + 4) * GBN;
            const int cb = wn * 32 + g, sw = tig * 8;
#pragma unroll
            for (int ni = 0; ni < 4; ni++) {
                b[ni][0] = Bp0[(cb + ni * 8) ^ sw];
                b[ni][1] = Bp1[(cb + ni * 8) ^ sw];
            }
#pragma unroll
            for (int mi = 0; mi < 2; mi++)
#pragma unroll
                for (int ni = 0; ni < 4; ni++)
                    MMA_TF32(acc[mi][ni], a[mi], b[ni]);
        }

        if (t + 1 < GNT) {
            const int nxt = cur ^ 1;
#pragma unroll
            for (int i = 0; i < 4; i++) {
                int idx = tid + i * 256, row = idx >> 5, c4 = idx & 31;
                int col = (c4 * 4) ^ ((row & 3) * 8);
                uint4 v = make_uint4(f2tf(breg[i].x), f2tf(breg[i].y), f2tf(breg[i].z), f2tf(breg[i].w));
                *(uint4*)&Bs[nxt][row * GBN + col] = v;
            }
#pragma unroll
            for (int i = 0; i < 2; i++) {
                int idx = tid * 2 + i, row = idx >> 3, kc = (idx & 7) * 4;
                int col = kc ^ ((row & 7) * 4);
                uint4 v = make_uint4(f2tf(areg[i].x), f2tf(areg[i].y), f2tf(areg[i].z), f2tf(areg[i].w));
                *(uint4*)&As[nxt][row * GBK + col] = v;
            }
            __syncthreads();
        }
    }

#pragma unroll
    for (int mi = 0; mi < 2; mi++) {
        int m = m0 + wm * 32 + mi * 16 + g;
#pragma unroll
        for (int ni = 0; ni < 4; ni++) {
            int n = n0 + wn * 32 + ni * 8 + tig * 2;
            float2 v0 = make_float2(acc[mi][ni][0], acc[mi][ni][1]);
            float2 v1 = make_float2(acc[mi][ni][2], acc[mi][ni][3]);
            *(float2*)&Cb[(size_t)m * N + n]       = v0;
            *(float2*)&Cb[(size_t)(m + 8) * N + n] = v1;
        }
    }
}

// ---------------------------------------------------------------------------
// Depthwise 3x3 for V channels only. 16 output rows per block, 256 threads.
// Input: g_qkv v-stripe; output: compact g_v [NB*C][HW].
// ---------------------------------------------------------------------------
#define DWR 16
__global__ __launch_bounds__(256) void dwv_kernel(
    const float* __restrict__ qkv, float* __restrict__ vout, const float* __restrict__ wdw)
{
    const int band = blockIdx.x;            // 0..HH/DWR-1
    const int bc   = blockIdx.y;            // 0..NB*C-1
    const int b    = bc / C, c = bc % C;
    const int tid  = threadIdx.x;
    const int y0   = band * DWR;

    __shared__ float s[DWR + 2][WW + 4];
    const float* base = qkv + ((size_t)b * C3 + 2 * C + c) * HW;

    for (int i = tid; i < (DWR + 2) * 32; i += 256) {
        int r = i >> 5, c4 = i & 31;
        int yy = y0 - 1 + r;
        float4 v = (yy >= 0 && yy < HH) ? *(const float4*)&base[yy * WW + c4 * 4]
                                        : make_float4(0.f, 0.f, 0.f, 0.f);
        s[r][c4 * 4 + 1] = v.x;
        s[r][c4 * 4 + 2] = v.y;
        s[r][c4 * 4 + 3] = v.z;
        s[r][c4 * 4 + 4] = v.w;
    }
    if (tid < DWR + 2) { s[tid][0] = 0.f; s[tid][WW + 1] = 0.f; }

    float w[9];
#pragma unroll
    for (int i = 0; i < 9; i++) w[i] = __ldg(&wdw[(2 * C + c) * 9 + i]);
    __syncthreads();

    const int lane = tid & 31;
    for (int r = tid >> 5; r < DWR; r += 8) {
        float* orow = vout + (size_t)bc * HW + (y0 + r) * WW;
#pragma unroll
        for (int j = 0; j < 4; j++) {
            int cc = lane + j * 32;
            float acc = 0.f;
#pragma unroll
            for (int dy = 0; dy < 3; dy++)
#pragma unroll
                for (int dx = 0; dx < 3; dx++)
                    acc += w[dy * 3 + dx] * s[r + dy][cc + dx];
            orow[cc] = acc;
        }
    }
}

// ---------------------------------------------------------------------------
// FUSED dw + score partials: per (split, b, head), apply depthwise 3x3 to
// q,k on the fly from g_qkv, accumulate 48x48 Q.K^T + sum-of-squares.
// Each block covers 4 image rows (= 512 spatial), chunks of 32 columns.
// ---------------------------------------------------------------------------
__global__ __launch_bounds__(256) void score_fused_kernel(
    const float* __restrict__ qkv, const float* __restrict__ wdw)
{
    const int split = blockIdx.x;           // 0..31  -> rows 4*split..+3
    const int unit  = blockIdx.y;           // b*NH + head
    const int b = unit >> 2, hd = unit & 3;
    const float* qb = qkv + ((size_t)b * C3 + hd * CH) * HW;
    const float* kb = qb + (size_t)C * HW;

    __shared__ float raw[CH][3][36];        // halo tile (reused q then k)
    __shared__ float qs[CH][33], ks[CH][33];
    __shared__ float wq[CH][9], wk[CH][9];

    const int tid = threadIdx.x, tx = tid & 15, ty = tid >> 4;

    for (int e = tid; e < CH * 9; e += 256) {
        int ch = e / 9, t = e % 9;
        wq[ch][t] = wdw[(hd * CH + ch) * 9 + t];
        wk[ch][t] = wdw[(C + hd * CH + ch) * 9 + t];
    }

    float acc[3][3] = {{0.f,0.f,0.f},{0.f,0.f,0.f},{0.f,0.f,0.f}};
    float nacc = 0.f;

    for (int ry = 0; ry < 4; ry++) {
        const int y = split * 4 + ry;
        for (int c0 = 0; c0 < WW; c0 += 32) {
            // ---- q: load halo, apply dw ----
            __syncthreads();                 // protect qs/ks & raw from prev iter
            for (int i = tid; i < CH * 108; i += 256) {
                int ch = i / 108, rem = i % 108;
                int r = rem / 36, cc = rem % 36;
                int yy = y - 1 + r, xx = c0 - 1 + cc;
                raw[ch][r][cc] = (yy >= 0 && yy < HH && xx >= 0 && xx < WW)
                                 ? qb[(size_t)ch * HW + yy * WW + xx] : 0.f;
            }
            __syncthreads();
            for (int i = tid; i < CH * 32; i += 256) {
                int ch = i >> 5, cc = i & 31;
                float a = 0.f;
#pragma unroll
                for (int dy = 0; dy < 3; dy++)
#pragma unroll
                    for (int dx = 0; dx < 3; dx++)
                        a += wq[ch][dy * 3 + dx] * raw[ch][dy][cc + dx];
                qs[ch][cc] = a;
            }
            __syncthreads();
            // ---- k: load halo, apply dw ----
            for (int i = tid; i < CH * 108; i += 256) {
                int ch = i / 108, rem = i % 108;
                int r = rem / 36, cc = rem % 36;
                int yy = y - 1 + r, xx = c0 - 1 + cc;
                raw[ch][r][cc] = (yy >= 0 && yy < HH && xx >= 0 && xx < WW)
                                 ? kb[(size_t)ch * HW + yy * WW + xx] : 0.f;
            }
            __syncthreads();
            for (int i = tid; i < CH * 32; i += 256) {
                int ch = i >> 5, cc = i & 31;
                float a = 0.f;
#pragma unroll
                for (int dy = 0; dy < 3; dy++)
#pragma unroll
                    for (int dx = 0; dx < 3; dx++)
                        a += wk[ch][dy * 3 + dx] * raw[ch][dy][cc + dx];
                ks[ch][cc] = a;
            }
            __syncthreads();

            // ---- sum-of-squares + 48x48 outer-product accumulation ----
            if (tid < 2 * CH) {
                int r = (tid < CH) ? tid : (tid - CH);
                const float* row = (tid < CH) ? qs[r] : ks[r];
#pragma unroll
                for (int j = 0; j < 32; j++) { float v = row[j]; nacc += v * v; }
            }
#pragma unroll 4
            for (int j = 0; j < 32; j++) {
                float q0 = qs[3 * ty + 0][j], q1 = qs[3 * ty + 1][j], q2 = qs[3 * ty + 2][j];
                float k0 = ks[3 * tx + 0][j], k1 = ks[3 * tx + 1][j], k2 = ks[3 * tx + 2][j];
                acc[0][0] += q0 * k0; acc[0][1] += q0 * k1; acc[0][2] += q0 * k2;
                acc[1][0] += q1 * k0; acc[1][1] += q1 * k1; acc[1][2] += q1 * k2;
                acc[2][0] += q2 * k0; acc[2][1] += q2 * k1; acc[2][2] += q2 * k2;
            }
        }
    }

    float* part = g_part + ((size_t)split * NB * NH + unit) * PART_STRIDE;
#pragma unroll
    for (int i = 0; i < 3; i++)
#pragma unroll
        for (int j = 0; j < 3; j++)
            part[(3 * ty + i) * CH + (3 * tx + j)] = acc[i][j];
    if (tid < 2 * CH) part[CH * CH + tid] = nacc;
}

// ---------------------------------------------------------------------------
// Reduce partials, apply 1/(|q||k|) * temperature, row softmax. 32 blocks.
// ---------------------------------------------------------------------------
__global__ __launch_bounds__(256) void softmax_kernel(const float* __restrict__ temperature)
{
    int unit = blockIdx.x;
    int hd = unit & 3;
    __shared__ float S[CH][CH];
    __shared__ float rq[CH], rk[CH];
    int tid = threadIdx.x;

    for (int e = tid; e < CH * CH; e += 256) {
        float s = 0.f;
#pragma unroll
        for (int p = 0; p < SPLIT; p++)
            s += g_part[((size_t)p * NB * NH + unit) * PART_STRIDE + e];
        S[e / CH][e % CH] = s;
    }
    if (tid < 2 * CH) {
        float s = 0.f;
#pragma unroll
        for (int p = 0; p < SPLIT; p++)
            s += g_part[((size_t)p * NB * NH + unit) * PART_STRIDE + CH * CH + tid];
        float inv = 1.f / fmaxf(sqrtf(s), 1e-12f);
        if (tid < CH) rq[tid] = inv; else rk[tid - CH] = inv;
    }
    __syncthreads();

    float temp = temperature[hd];
    if (tid < CH) {
        int i = tid;
        float row[CH];
        float mx = -3.402823466e38f;
#pragma unroll
        for (int j = 0; j < CH; j++) {
            float v = S[i][j] * rq[i] * rk[j] * temp;
            row[j] = v;
            mx = fmaxf(mx, v);
        }
        float sum = 0.f;
#pragma unroll
        for (int j = 0; j < CH; j++) { row[j] = expf(row[j] - mx); sum += row[j]; }
        float inv = 1.f / sum;
#pragma unroll
        for (int j = 0; j < CH; j++)
            g_score[(size_t)unit * CH * CH + i * CH + j] = row[j] * inv;
    }
}

// ---------------------------------------------------------------------------
// P_b[o, hd*48+d] = sum_c Wproj[o, hd*48+c] * score[b,hd][c,d]
// ---------------------------------------------------------------------------
__global__ __launch_bounds__(256) void pmat_kernel(const float* __restrict__ wproj)
{
    int unit = blockIdx.x;
    int b = unit >> 2, hd = unit & 3;
    __shared__ float sc[CH][CH];
    __shared__ float wp[C][CH];
    int tid = threadIdx.x;

    for (int e = tid; e < CH * CH; e += 256)
        sc[e / CH][e % CH] = g_score[(size_t)unit * CH * CH + e];
    for (int e = tid; e < C * CH; e += 256) {
        int o = e / CH, c = e % CH;
        wp[o][c] = wproj[o * C + hd * CH + c];
    }
    __syncthreads();

    for (int e = tid; e < C * CH; e += 256) {
        int o = e / CH, d = e % CH;
        float acc = 0.f;
#pragma unroll
        for (int c = 0; c < CH; c++) acc += wp[o][c] * sc[c][d];
        g_P[((size_t)b * C + o) * C + hd * CH + d] = acc;
    }
}

// ---------------------------------------------------------------------------
extern "C" void kernel_launch(void* const* d_in, const int* in_sizes, int n_in,
                              void* d_out, int out_size)
{
    (void)in_sizes; (void)n_in; (void)out_size;
    const float* x      = (const float*)d_in[0];
    const float* w_qkv  = (const float*)d_in[1];
    const float* w_dw   = (const float*)d_in[2];
    const float* w_proj = (const float*)d_in[3];
    const float* temp   = (const float*)d_in[4];
    float* out = (float*)d_out;

    float *qkv, *vbuf, *pmat;
    cudaGetSymbolAddress((void**)&qkv,  g_qkv);
    cudaGetSymbolAddress((void**)&vbuf, g_v);
    cudaGetSymbolAddress((void**)&pmat, g_P);

    // 1) qkv = W_qkv (576x192) * x[b] (192x16384)  — TF32 tensor cores
    gemm_tf32_kernel<<<dim3(HW / GBN, C3 / GBM, NB), 256>>>(
        w_qkv, x, qkv, C3, HW, 0, (size_t)KD * HW);
    // 2) depthwise 3x3 on V channels only -> compact g_v
    dwv_kernel<<<dim3(HH / DWR, NB * C), 256>>>(qkv, vbuf, w_dw);
    // 3) fused dw(q,k) + split-K score partials
    score_fused_kernel<<<dim3(SPLIT, NB * NH), 256>>>(qkv, w_dw);
    // 4) normalize + temperature + softmax
    softmax_kernel<<<NB * NH, 256>>>(temp);
    // 5) P_b = W_proj @ blockdiag(score_b)
    pmat_kernel<<<NB * NH, 256>>>(w_proj);
    // 6) out = P_b (192x192) * v[b] (192x16384)  — TF32 tensor cores
    gemm_tf32_kernel<<<dim3(HW / GBN, C / GBM, NB), 256>>>(
        pmat, vbuf, out, C, HW, (size_t)C * C, (size_t)C * HW);
}

// round 7
// speedup vs baseline: 1.3173x; 1.3173x over previous
#include <cuda_runtime.h>
#include <cuda_fp16.h>
#include <math.h>

#define NB 8
#define C 192
#define C3 576
#define NH 4
#define CH 48
#define HH 128
#define WW 128
#define HW 16384
#define SPLIT 32
#define PART_STRIDE (CH*CH + 2*CH)   /* 2400 */

// Scratch (device globals: no allocation allowed in kernel_launch)
__device__ __half g_qkv[NB*C3*HW];                 // 151 MB: 1x1 conv output (fp16)
__device__ __half g_dw [NB*C3*HW];                 // 151 MB: depthwise output (fp16)
__device__ float g_part[SPLIT*NB*NH*PART_STRIDE];  // split-K partials
__device__ float g_score[NB*NH*CH*CH];             // softmaxed scores
__device__ float g_P   [NB*C*C];                   // fused W_proj @ blockdiag(score)

// ===========================================================================
// TF32 tensor-core GEMM building blocks.
// BM=64, BN=128, BK=32, 256 threads (8 warps 2x4), warp tile 32x32,
// double-buffered smem. A fp32 [M,192] row-major; smem layouts:
//   As: [m][k ^ ((m&7)*4)] stride 32; Bs: [k][n ^ ((k&3)*8)] stride 128.
// ===========================================================================
#define GBM 64
#define GBN 128
#define GBK 32
#define KD  192
#define GNT (KD/GBK)   /* 6 */

__device__ __forceinline__ unsigned f2tf(float f) {
    unsigned u; asm("cvt.rna.tf32.f32 %0, %1;" : "=r"(u) : "f"(f)); return u;
}

#define MMA_TF32(d, av, bv)                                                   \
  asm("mma.sync.aligned.m16n8k8.row.col.f32.tf32.tf32.f32 "                   \
      "{%0,%1,%2,%3}, {%4,%5,%6,%7}, {%8,%9}, {%0,%1,%2,%3};"                 \
      : "+f"(d[0]), "+f"(d[1]), "+f"(d[2]), "+f"(d[3])                        \
      : "r"(av[0]), "r"(av[1]), "r"(av[2]), "r"(av[3]),                       \
        "r"(bv[0]), "r"(bv[1]))

// ---- shared compute phase (reads As/Bs fragments, 8 MMAs x 4 ksteps) ----
#define GEMM_COMPUTE(As_, Bs_)                                                \
  do {                                                                        \
    _Pragma("unroll")                                                         \
    for (int kk = 0; kk < 4; kk++) {                                          \
        unsigned a[2][4], b[4][2];                                            \
        const int asw = g * 4;                                                \
        const int col0 = (kk * 8 + tig) ^ asw;                                \
        const int col1 = (kk * 8 + 4 + tig) ^ asw;                            \
        _Pragma("unroll")                                                     \
        for (int mi = 0; mi < 2; mi++) {                                      \
            int r0 = (wm * 32 + mi * 16 + g) * GBK;                           \
            int r1 = r0 + 8 * GBK;                                            \
            a[mi][0] = (As_)[r0 + col0];                                      \
            a[mi][1] = (As_)[r1 + col0];                                      \
            a[mi][2] = (As_)[r0 + col1];                                      \
            a[mi][3] = (As_)[r1 + col1];                                      \
        }                                                                     \
        const unsigned* Bp0 = (Bs_) + (kk * 8 + tig) * GBN;                   \
        const unsigned* Bp1 = (Bs_) + (kk * 8 + tig + 4) * GBN;               \
        const int cb = wn * 32 + g, sw = tig * 8;                             \
        _Pragma("unroll")                                                     \
        for (int ni = 0; ni < 4; ni++) {                                      \
            b[ni][0] = Bp0[(cb + ni * 8) ^ sw];                               \
            b[ni][1] = Bp1[(cb + ni * 8) ^ sw];                               \
        }                                                                     \
        _Pragma("unroll")                                                     \
        for (int mi = 0; mi < 2; mi++)                                        \
            _Pragma("unroll")                                                 \
            for (int ni = 0; ni < 4; ni++)                                    \
                MMA_TF32(acc[mi][ni], a[mi], b[ni]);                          \
    }                                                                         \
  } while (0)

// ---------------------------------------------------------------------------
// GEMM 1: A fp32 (shared weights), B fp32 (batched), C fp16.
//   qkv = W_qkv (576x192) * x[b] (192x16384)
// ---------------------------------------------------------------------------
__global__ __launch_bounds__(256) void gemm_f32b_h_kernel(
    const float* __restrict__ A, const float* __restrict__ Bm, __half* __restrict__ Cm,
    int M, int N, size_t bstride)
{
    __shared__ unsigned As[2][GBM * GBK];
    __shared__ unsigned Bs[2][GBK * GBN];

    const int tid  = threadIdx.x;
    const int lane = tid & 31, wid = tid >> 5;
    const int wm = wid & 1, wn = wid >> 1;
    const int g = lane >> 2, tig = lane & 3;

    const int m0 = blockIdx.y * GBM, n0 = blockIdx.x * GBN;
    const float* Ab = A + (size_t)m0 * KD;
    const float* Bb = Bm + bstride * blockIdx.z + n0;
    __half*      Cb = Cm + (size_t)blockIdx.z * M * N;

    float acc[2][4][4];
#pragma unroll
    for (int mi = 0; mi < 2; mi++)
#pragma unroll
        for (int ni = 0; ni < 4; ni++)
#pragma unroll
            for (int j = 0; j < 4; j++) acc[mi][ni][j] = 0.f;

    float4 areg[2], breg[4];

#pragma unroll
    for (int i = 0; i < 2; i++) {
        int idx = tid * 2 + i, row = idx >> 3, kc = (idx & 7) * 4;
        areg[i] = *(const float4*)&Ab[(size_t)row * KD + kc];
    }
#pragma unroll
    for (int i = 0; i < 4; i++) {
        int idx = tid + i * 256, row = idx >> 5, c4 = idx & 31;
        breg[i] = *(const float4*)&Bb[(size_t)row * N + c4 * 4];
    }
#pragma unroll
    for (int i = 0; i < 2; i++) {
        int idx = tid * 2 + i, row = idx >> 3, kc = (idx & 7) * 4;
        int col = kc ^ ((row & 7) * 4);
        uint4 v = make_uint4(f2tf(areg[i].x), f2tf(areg[i].y), f2tf(areg[i].z), f2tf(areg[i].w));
        *(uint4*)&As[0][row * GBK + col] = v;
    }
#pragma unroll
    for (int i = 0; i < 4; i++) {
        int idx = tid + i * 256, row = idx >> 5, c4 = idx & 31;
        int col = (c4 * 4) ^ ((row & 3) * 8);
        uint4 v = make_uint4(f2tf(breg[i].x), f2tf(breg[i].y), f2tf(breg[i].z), f2tf(breg[i].w));
        *(uint4*)&Bs[0][row * GBN + col] = v;
    }
    __syncthreads();

#pragma unroll
    for (int t = 0; t < GNT; t++) {
        const int cur = t & 1;
        if (t + 1 < GNT) {
            int kofs = (t + 1) * GBK;
#pragma unroll
            for (int i = 0; i < 4; i++) {
                int idx = tid + i * 256, row = idx >> 5, c4 = idx & 31;
                breg[i] = *(const float4*)&Bb[(size_t)(kofs + row) * N + c4 * 4];
            }
#pragma unroll
            for (int i = 0; i < 2; i++) {
                int idx = tid * 2 + i, row = idx >> 3, kc = (idx & 7) * 4;
                areg[i] = *(const float4*)&Ab[(size_t)row * KD + kofs + kc];
            }
        }

        GEMM_COMPUTE(As[cur], Bs[cur]);

        if (t + 1 < GNT) {
            const int nxt = cur ^ 1;
#pragma unroll
            for (int i = 0; i < 4; i++) {
                int idx = tid + i * 256, row = idx >> 5, c4 = idx & 31;
                int col = (c4 * 4) ^ ((row & 3) * 8);
                uint4 v = make_uint4(f2tf(breg[i].x), f2tf(breg[i].y), f2tf(breg[i].z), f2tf(breg[i].w));
                *(uint4*)&Bs[nxt][row * GBN + col] = v;
            }
#pragma unroll
            for (int i = 0; i < 2; i++) {
                int idx = tid * 2 + i, row = idx >> 3, kc = (idx & 7) * 4;
                int col = kc ^ ((row & 7) * 4);
                uint4 v = make_uint4(f2tf(areg[i].x), f2tf(areg[i].y), f2tf(areg[i].z), f2tf(areg[i].w));
                *(uint4*)&As[nxt][row * GBK + col] = v;
            }
            __syncthreads();
        }
    }

#pragma unroll
    for (int mi = 0; mi < 2; mi++) {
        int m = m0 + wm * 32 + mi * 16 + g;
#pragma unroll
        for (int ni = 0; ni < 4; ni++) {
            int n = n0 + wn * 32 + ni * 8 + tig * 2;
            *(__half2*)&Cb[(size_t)m * N + n] =
                __floats2half2_rn(acc[mi][ni][0], acc[mi][ni][1]);
            *(__half2*)&Cb[(size_t)(m + 8) * N + n] =
                __floats2half2_rn(acc[mi][ni][2], acc[mi][ni][3]);
        }
    }
}

// ---------------------------------------------------------------------------
// GEMM 2: A fp32 (batched), B fp16 (batched), C fp32.
//   out = P_b (192x192) * v[b] (192x16384)
// ---------------------------------------------------------------------------
__global__ __launch_bounds__(256) void gemm_h_f32c_kernel(
    const float* __restrict__ A, const __half* __restrict__ Bm, float* __restrict__ Cm,
    int M, int N, size_t astride, size_t bstride)
{
    __shared__ unsigned As[2][GBM * GBK];
    __shared__ unsigned Bs[2][GBK * GBN];

    const int tid  = threadIdx.x;
    const int lane = tid & 31, wid = tid >> 5;
    const int wm = wid & 1, wn = wid >> 1;
    const int g = lane >> 2, tig = lane & 3;

    const int m0 = blockIdx.y * GBM, n0 = blockIdx.x * GBN;
    const float*  Ab = A + astride * blockIdx.z + (size_t)m0 * KD;
    const __half* Bb = Bm + bstride * blockIdx.z + n0;
    float*        Cb = Cm + (size_t)blockIdx.z * M * N;

    float acc[2][4][4];
#pragma unroll
    for (int mi = 0; mi < 2; mi++)
#pragma unroll
        for (int ni = 0; ni < 4; ni++)
#pragma unroll
            for (int j = 0; j < 4; j++) acc[mi][ni][j] = 0.f;

    float4 areg[2];
    uint4  hreg[2];   // 8 halves each; 2*8*256 = 4096 halves = 32x128 tile

    // B loads: idx = tid + i*256 -> row = idx>>4 (16 chunks/row), c8 = idx&15
#pragma unroll
    for (int i = 0; i < 2; i++) {
        int idx = tid * 2 + i, row = idx >> 3, kc = (idx & 7) * 4;
        areg[i] = *(const float4*)&Ab[(size_t)row * KD + kc];
    }
#pragma unroll
    for (int i = 0; i < 2; i++) {
        int idx = tid + i * 256, row = idx >> 4, c8 = idx & 15;
        hreg[i] = *(const uint4*)&Bb[(size_t)row * N + c8 * 8];
    }
#pragma unroll
    for (int i = 0; i < 2; i++) {
        int idx = tid * 2 + i, row = idx >> 3, kc = (idx & 7) * 4;
        int col = kc ^ ((row & 7) * 4);
        uint4 v = make_uint4(f2tf(areg[i].x), f2tf(areg[i].y), f2tf(areg[i].z), f2tf(areg[i].w));
        *(uint4*)&As[0][row * GBK + col] = v;
    }
#pragma unroll
    for (int i = 0; i < 2; i++) {
        int idx = tid + i * 256, row = idx >> 4, c8 = idx & 15;
        int col = (c8 * 8) ^ ((row & 3) * 8);
        __half2 h0 = *(__half2*)&hreg[i].x, h1 = *(__half2*)&hreg[i].y;
        __half2 h2 = *(__half2*)&hreg[i].z, h3 = *(__half2*)&hreg[i].w;
        uint4 v0 = make_uint4(f2tf(__low2float(h0)), f2tf(__high2float(h0)),
                              f2tf(__low2float(h1)), f2tf(__high2float(h1)));
        uint4 v1 = make_uint4(f2tf(__low2float(h2)), f2tf(__high2float(h2)),
                              f2tf(__low2float(h3)), f2tf(__high2float(h3)));
        *(uint4*)&Bs[0][row * GBN + col]     = v0;
        *(uint4*)&Bs[0][row * GBN + col + 4] = v1;
    }
    __syncthreads();

#pragma unroll
    for (int t = 0; t < GNT; t++) {
        const int cur = t & 1;
        if (t + 1 < GNT) {
            int kofs = (t + 1) * GBK;
#pragma unroll
            for (int i = 0; i < 2; i++) {
                int idx = tid + i * 256, row = idx >> 4, c8 = idx & 15;
                hreg[i] = *(const uint4*)&Bb[(size_t)(kofs + row) * N + c8 * 8];
            }
#pragma unroll
            for (int i = 0; i < 2; i++) {
                int idx = tid * 2 + i, row = idx >> 3, kc = (idx & 7) * 4;
                areg[i] = *(const float4*)&Ab[(size_t)row * KD + kofs + kc];
            }
        }

        GEMM_COMPUTE(As[cur], Bs[cur]);

        if (t + 1 < GNT) {
            const int nxt = cur ^ 1;
#pragma unroll
            for (int i = 0; i < 2; i++) {
                int idx = tid + i * 256, row = idx >> 4, c8 = idx & 15;
                int col = (c8 * 8) ^ ((row & 3) * 8);
                __half2 h0 = *(__half2*)&hreg[i].x, h1 = *(__half2*)&hreg[i].y;
                __half2 h2 = *(__half2*)&hreg[i].z, h3 = *(__half2*)&hreg[i].w;
                uint4 v0 = make_uint4(f2tf(__low2float(h0)), f2tf(__high2float(h0)),
                                      f2tf(__low2float(h1)), f2tf(__high2float(h1)));
                uint4 v1 = make_uint4(f2tf(__low2float(h2)), f2tf(__high2float(h2)),
                                      f2tf(__low2float(h3)), f2tf(__high2float(h3)));
                *(uint4*)&Bs[nxt][row * GBN + col]     = v0;
                *(uint4*)&Bs[nxt][row * GBN + col + 4] = v1;
            }
#pragma unroll
            for (int i = 0; i < 2; i++) {
                int idx = tid * 2 + i, row = idx >> 3, kc = (idx & 7) * 4;
                int col = kc ^ ((row & 7) * 4);
                uint4 v = make_uint4(f2tf(areg[i].x), f2tf(areg[i].y), f2tf(areg[i].z), f2tf(areg[i].w));
                *(uint4*)&As[nxt][row * GBK + col] = v;
            }
            __syncthreads();
        }
    }

#pragma unroll
    for (int mi = 0; mi < 2; mi++) {
        int m = m0 + wm * 32 + mi * 16 + g;
#pragma unroll
        for (int ni = 0; ni < 4; ni++) {
            int n = n0 + wn * 32 + ni * 8 + tig * 2;
            *(float2*)&Cb[(size_t)m * N + n] =
                make_float2(acc[mi][ni][0], acc[mi][ni][1]);
            *(float2*)&Cb[(size_t)(m + 8) * N + n] =
                make_float2(acc[mi][ni][2], acc[mi][ni][3]);
        }
    }
}

// ---------------------------------------------------------------------------
// Depthwise 3x3 (fp16 in/out, fp32 math). 16 output rows per block.
// ---------------------------------------------------------------------------
#define DWR 16
__global__ __launch_bounds__(256) void dw_kernel(
    const __half* __restrict__ in, __half* __restrict__ out, const float* __restrict__ wdw)
{
    const int band = blockIdx.x;            // 0..HH/DWR-1
    const int bc   = blockIdx.y;            // 0..NB*C3-1
    const int ch   = bc % C3;
    const int tid  = threadIdx.x;
    const int y0   = band * DWR;

    __shared__ float s[DWR + 2][WW + 4];
    const __half* base = in + (size_t)bc * HW;

    // load 18 rows x 128 cols (16 chunks of 8 halves per row)
    for (int i = tid; i < (DWR + 2) * 16; i += 256) {
        int r = i >> 4, c8 = i & 15;
        int yy = y0 - 1 + r;
        float* d = &s[r][c8 * 8 + 1];
        if (yy >= 0 && yy < HH) {
            float4 rv = *(const float4*)(const void*)&base[yy * WW + c8 * 8];
            __half2 h0 = *(__half2*)&rv.x, h1 = *(__half2*)&rv.y;
            __half2 h2 = *(__half2*)&rv.z, h3 = *(__half2*)&rv.w;
            d[0] = __low2float(h0); d[1] = __high2float(h0);
            d[2] = __low2float(h1); d[3] = __high2float(h1);
            d[4] = __low2float(h2); d[5] = __high2float(h2);
            d[6] = __low2float(h3); d[7] = __high2float(h3);
        } else {
#pragma unroll
            for (int j = 0; j < 8; j++) d[j] = 0.f;
        }
    }
    if (tid < DWR + 2) { s[tid][0] = 0.f; s[tid][WW + 1] = 0.f; }

    float w[9];
#pragma unroll
    for (int i = 0; i < 9; i++) w[i] = __ldg(&wdw[ch * 9 + i]);
    __syncthreads();

    const int lane = tid & 31;
    for (int r = tid >> 5; r < DWR; r += 8) {
        __half* orow = out + (size_t)bc * HW + (y0 + r) * WW;
#pragma unroll
        for (int j = 0; j < 4; j++) {
            int cc = lane + j * 32;
            float acc = 0.f;
#pragma unroll
            for (int dy = 0; dy < 3; dy++)
#pragma unroll
                for (int dx = 0; dx < 3; dx++)
                    acc += w[dy * 3 + dx] * s[r + dy][cc + dx];
            orow[cc] = __float2half_rn(acc);
        }
    }
}

// ---------------------------------------------------------------------------
// Score partials (fp16 input, fp32 math): per (split, b, head) accumulate
// 48x48 Q.K^T over an s-range, plus per-row sum-of-squares.
// ---------------------------------------------------------------------------
__global__ __launch_bounds__(256) void score_partial_kernel(const __half* __restrict__ qkvd)
{
    int split = blockIdx.x;
    int unit  = blockIdx.y;
    int b = unit >> 2, hd = unit & 3;
    const __half* qb = qkvd + ((size_t)b * C3 + hd * CH) * HW;
    const __half* kb = qb + (size_t)C * HW;

    const int CS = 32;
    __shared__ float qs[CH][CS + 1], ks[CH][CS + 1];

    int tid = threadIdx.x, tx = tid & 15, ty = tid >> 4;
    float acc[3][3] = {{0.f,0.f,0.f},{0.f,0.f,0.f},{0.f,0.f,0.f}};
    float nacc = 0.f;

    int s_beg = split * (HW / SPLIT);
    int s_end = s_beg + (HW / SPLIT);
    for (int s0 = s_beg; s0 < s_end; s0 += CS) {
#pragma unroll
        for (int i = 0; i < (CH * CS) / 256; i++) {
            int idx = tid + i * 256;
            int r = idx >> 5, c = idx & 31;
            qs[r][c] = __half2float(qb[(size_t)r * HW + s0 + c]);
            ks[r][c] = __half2float(kb[(size_t)r * HW + s0 + c]);
        }
        __syncthreads();

        if (tid < 2 * CH) {
            int r = (tid < CH) ? tid : (tid - CH);
            const float* row = (tid < CH) ? qs[r] : ks[r];
#pragma unroll
            for (int j = 0; j < CS; j++) { float v = row[j]; nacc += v * v; }
        }

#pragma unroll 4
        for (int j = 0; j < CS; j++) {
            float q0 = qs[3 * ty + 0][j], q1 = qs[3 * ty + 1][j], q2 = qs[3 * ty + 2][j];
            float k0 = ks[3 * tx + 0][j], k1 = ks[3 * tx + 1][j], k2 = ks[3 * tx + 2][j];
            acc[0][0] += q0 * k0; acc[0][1] += q0 * k1; acc[0][2] += q0 * k2;
            acc[1][0] += q1 * k0; acc[1][1] += q1 * k1; acc[1][2] += q1 * k2;
            acc[2][0] += q2 * k0; acc[2][1] += q2 * k1; acc[2][2] += q2 * k2;
        }
        __syncthreads();
    }

    float* part = g_part + ((size_t)split * NB * NH + unit) * PART_STRIDE;
#pragma unroll
    for (int i = 0; i < 3; i++)
#pragma unroll
        for (int j = 0; j < 3; j++)
            part[(3 * ty + i) * CH + (3 * tx + j)] = acc[i][j];
    if (tid < 2 * CH) part[CH * CH + tid] = nacc;
}

// ---------------------------------------------------------------------------
// Reduce partials, apply 1/(|q||k|) * temperature, row softmax. 32 blocks.
// ---------------------------------------------------------------------------
__global__ __launch_bounds__(256) void softmax_kernel(const float* __restrict__ temperature)
{
    int unit = blockIdx.x;
    int hd = unit & 3;
    __shared__ float S[CH][CH];
    __shared__ float rq[CH], rk[CH];
    int tid = threadIdx.x;

    for (int e = tid; e < CH * CH; e += 256) {
        float s = 0.f;
#pragma unroll
        for (int p = 0; p < SPLIT; p++)
            s += g_part[((size_t)p * NB * NH + unit) * PART_STRIDE + e];
        S[e / CH][e % CH] = s;
    }
    if (tid < 2 * CH) {
        float s = 0.f;
#pragma unroll
        for (int p = 0; p < SPLIT; p++)
            s += g_part[((size_t)p * NB * NH + unit) * PART_STRIDE + CH * CH + tid];
        float inv = 1.f / fmaxf(sqrtf(s), 1e-12f);
        if (tid < CH) rq[tid] = inv; else rk[tid - CH] = inv;
    }
    __syncthreads();

    float temp = temperature[hd];
    if (tid < CH) {
        int i = tid;
        float row[CH];
        float mx = -3.402823466e38f;
#pragma unroll
        for (int j = 0; j < CH; j++) {
            float v = S[i][j] * rq[i] * rk[j] * temp;
            row[j] = v;
            mx = fmaxf(mx, v);
        }
        float sum = 0.f;
#pragma unroll
        for (int j = 0; j < CH; j++) { row[j] = expf(row[j] - mx); sum += row[j]; }
        float inv = 1.f / sum;
#pragma unroll
        for (int j = 0; j < CH; j++)
            g_score[(size_t)unit * CH * CH + i * CH + j] = row[j] * inv;
    }
}

// ---------------------------------------------------------------------------
// P_b[o, hd*48+d] = sum_c Wproj[o, hd*48+c] * score[b,hd][c,d]
// ---------------------------------------------------------------------------
__global__ __launch_bounds__(256) void pmat_kernel(const float* __restrict__ wproj)
{
    int unit = blockIdx.x;
    int b = unit >> 2, hd = unit & 3;
    __shared__ float sc[CH][CH];
    __shared__ float wp[C][CH];
    int tid = threadIdx.x;

    for (int e = tid; e < CH * CH; e += 256)
        sc[e / CH][e % CH] = g_score[(size_t)unit * CH * CH + e];
    for (int e = tid; e < C * CH; e += 256) {
        int o = e / CH, c = e % CH;
        wp[o][c] = wproj[o * C + hd * CH + c];
    }
    __syncthreads();

    for (int e = tid; e < C * CH; e += 256) {
        int o = e / CH, d = e % CH;
        float acc = 0.f;
#pragma unroll
        for (int c = 0; c < CH; c++) acc += wp[o][c] * sc[c][d];
        g_P[((size_t)b * C + o) * C + hd * CH + d] = acc;
    }
}

// ---------------------------------------------------------------------------
extern "C" void kernel_launch(void* const* d_in, const int* in_sizes, int n_in,
                              void* d_out, int out_size)
{
    (void)in_sizes; (void)n_in; (void)out_size;
    const float* x      = (const float*)d_in[0];
    const float* w_qkv  = (const float*)d_in[1];
    const float* w_dw   = (const float*)d_in[2];
    const float* w_proj = (const float*)d_in[3];
    const float* temp   = (const float*)d_in[4];
    float* out = (float*)d_out;

    __half *qkv, *dwb;
    float *pmat;
    cudaGetSymbolAddress((void**)&qkv,  g_qkv);
    cudaGetSymbolAddress((void**)&dwb,  g_dw);
    cudaGetSymbolAddress((void**)&pmat, g_P);

    // 1) qkv = W_qkv (576x192) * x[b] (192x16384)  — TF32, fp16 output
    gemm_f32b_h_kernel<<<dim3(HW / GBN, C3 / GBM, NB), 256>>>(
        w_qkv, x, qkv, C3, HW, (size_t)KD * HW);
    // 2) depthwise 3x3 on all channels (fp16 -> fp16)
    dw_kernel<<<dim3(HH / DWR, NB * C3), 256>>>(qkv, dwb, w_dw);
    // 3) split-K score partials (fp16 input)
    score_partial_kernel<<<dim3(SPLIT, NB * NH), 256>>>(dwb);
    // 4) normalize + temperature + softmax
    softmax_kernel<<<NB * NH, 256>>>(temp);
    // 5) P_b = W_proj @ blockdiag(score_b)
    pmat_kernel<<<NB * NH, 256>>>(w_proj);
    // 6) out = P_b (192x192) * v[b] (192x16384)  — TF32, fp16 B input
    gemm_h_f32c_kernel<<<dim3(HW / GBN, C / GBM, NB), 256>>>(
        pmat, dwb + (size_t)2 * C * HW, out, C, HW,
        (size_t)C * C, (size_t)C3 * HW);
}

// round 8
// speedup vs baseline: 1.6006x; 1.2151x over previous
#include <cuda_runtime.h>
#include <cuda_fp16.h>
#include <math.h>

#define NB 8
#define C 192
#define C3 576
#define NH 4
#define CH 48
#define HH 128
#define WW 128
#define HW 16384
#define SPLIT 32
#define PART_STRIDE (CH*CH + 2*CH)   /* 2400 */

// Scratch (device globals: no allocation allowed in kernel_launch)
__device__ __half g_qkv[NB*C3*HW];                 // 151 MB
__device__ __half g_dw [NB*C3*HW];                 // 151 MB
__device__ float g_part[SPLIT*NB*NH*PART_STRIDE];
__device__ float g_score[NB*NH*CH*CH];
__device__ float g_P   [NB*C*C];

// ===========================================================================
// FP16 tensor-core GEMM (m16n8k16, fp32 accum).
// BM=64, BN=128, BK=32, 256 threads (8 warps 2x4), warp tile 32x32.
// As: [64][32] halves, 16B-chunk swizzle ((m&1)*4+c)^((m>>1)&7).
// Bs: [32][128] halves, 16B-chunk swizzle c^(k&7). Double buffered (24KB).
// ===========================================================================
#define GBM 64
#define GBN 128
#define GBK 32
#define KD  192
#define GNT (KD/GBK)   /* 6 */

__device__ __forceinline__ unsigned h2u(__half2 h) {
    return *(unsigned*)&h;
}
__device__ __forceinline__ void ldsm_x4(unsigned& r0, unsigned& r1, unsigned& r2,
                                        unsigned& r3, unsigned addr) {
    asm volatile("ldmatrix.sync.aligned.m8n8.x4.shared.b16 {%0,%1,%2,%3}, [%4];"
        : "=r"(r0), "=r"(r1), "=r"(r2), "=r"(r3) : "r"(addr));
}
__device__ __forceinline__ void ldsm_x4_t(unsigned& r0, unsigned& r1, unsigned& r2,
                                          unsigned& r3, unsigned addr) {
    asm volatile("ldmatrix.sync.aligned.m8n8.x4.trans.shared.b16 {%0,%1,%2,%3}, [%4];"
        : "=r"(r0), "=r"(r1), "=r"(r2), "=r"(r3) : "r"(addr));
}

#define MMA_F16(d, av, bv)                                                    \
  asm("mma.sync.aligned.m16n8k16.row.col.f32.f16.f16.f32 "                    \
      "{%0,%1,%2,%3}, {%4,%5,%6,%7}, {%8,%9}, {%0,%1,%2,%3};"                 \
      : "+f"(d[0]), "+f"(d[1]), "+f"(d[2]), "+f"(d[3])                        \
      : "r"(av[0]), "r"(av[1]), "r"(av[2]), "r"(av[3]),                       \
        "r"(bv[0]), "r"(bv[1]))

// A smem chunk slot (uint4 index) for logical (m, chunk c in 0..3)
__device__ __forceinline__ int a_slot(int m, int c) {
    return (m >> 1) * 8 + ((((m & 1) << 2) + c) ^ ((m >> 1) & 7));
}
// B smem chunk slot for logical (k, chunk c in 0..15)
__device__ __forceinline__ int b_slot(int k, int c) {
    return k * 16 + (c ^ (k & 7));
}

// ---- fragment compute: 2 k16 steps, 8 MMAs each ----
#define GEMM_COMPUTE_F16(asbase_, bsbase_)                                    \
  do {                                                                        \
    _Pragma("unroll")                                                         \
    for (int kk = 0; kk < 2; kk++) {                                          \
        unsigned a[2][4], b[4][2];                                            \
        _Pragma("unroll")                                                     \
        for (int mi = 0; mi < 2; mi++) {                                      \
            int m = wm * 32 + mi * 16 + a_sel;                                \
            int c = 2 * kk + a_hi;                                            \
            ldsm_x4(a[mi][0], a[mi][1], a[mi][2], a[mi][3],                   \
                    (asbase_) + a_slot(m, c) * 16);                           \
        }                                                                     \
        _Pragma("unroll")                                                     \
        for (int np = 0; np < 2; np++) {                                      \
            int k = kk * 16 + b_koff;                                         \
            int cb = wn * 4 + 2 * np + b_nsel;                                \
            ldsm_x4_t(b[2*np][0], b[2*np][1], b[2*np+1][0], b[2*np+1][1],     \
                      (bsbase_) + b_slot(k, cb) * 16);                        \
        }                                                                     \
        _Pragma("unroll")                                                     \
        for (int mi = 0; mi < 2; mi++)                                        \
            _Pragma("unroll")                                                 \
            for (int ni = 0; ni < 4; ni++)                                    \
                MMA_F16(acc[mi][ni], a[mi], b[ni]);                           \
    }                                                                         \
  } while (0)

// pack 8 fp32 (two float4) -> uint4 of halves
__device__ __forceinline__ uint4 pack8(float4 f0, float4 f1) {
    uint4 v;
    v.x = h2u(__floats2half2_rn(f0.x, f0.y));
    v.y = h2u(__floats2half2_rn(f0.z, f0.w));
    v.z = h2u(__floats2half2_rn(f1.x, f1.y));
    v.w = h2u(__floats2half2_rn(f1.z, f1.w));
    return v;
}

// ---------------------------------------------------------------------------
// GEMM 1: A fp32 (shared weights), B fp32 (batched), C fp16.
// ---------------------------------------------------------------------------
__global__ __launch_bounds__(256) void gemm_f32b_h_kernel(
    const float* __restrict__ A, const float* __restrict__ Bm, __half* __restrict__ Cm,
    int M, int N, size_t bstride)
{
    __shared__ __align__(16) __half As[2][GBM * GBK];
    __shared__ __align__(16) __half Bs[2][GBK * GBN];

    const int tid  = threadIdx.x;
    const int lane = tid & 31, wid = tid >> 5;
    const int wm = wid & 1, wn = wid >> 1;
    const int g = lane >> 2, tig = lane & 3;
    const int a_sel = lane & 15, a_hi = lane >> 4;
    const int b_koff = lane & 15, b_nsel = lane >> 4;

    const int m0 = blockIdx.y * GBM, n0 = blockIdx.x * GBN;
    const float* Ab = A + (size_t)m0 * KD;
    const float* Bb = Bm + bstride * blockIdx.z + n0;
    __half*      Cb = Cm + (size_t)blockIdx.z * M * N;

    unsigned asbase[2] = { (unsigned)__cvta_generic_to_shared(As[0]),
                           (unsigned)__cvta_generic_to_shared(As[1]) };
    unsigned bsbase[2] = { (unsigned)__cvta_generic_to_shared(Bs[0]),
                           (unsigned)__cvta_generic_to_shared(Bs[1]) };
    uint4* As4[2] = { (uint4*)As[0], (uint4*)As[1] };
    uint4* Bs4[2] = { (uint4*)Bs[0], (uint4*)Bs[1] };

    float acc[2][4][4];
#pragma unroll
    for (int mi = 0; mi < 2; mi++)
#pragma unroll
        for (int ni = 0; ni < 4; ni++)
#pragma unroll
            for (int j = 0; j < 4; j++) acc[mi][ni][j] = 0.f;

    // A: 1 chunk/thread (m = tid>>2, c = tid&3); B: 2 chunks/thread
    const int am = tid >> 2, ac = tid & 3;
    float4 ar0, ar1, br0[2], br1[2];

    // prologue
    ar0 = *(const float4*)&Ab[(size_t)am * KD + ac * 8];
    ar1 = *(const float4*)&Ab[(size_t)am * KD + ac * 8 + 4];
#pragma unroll
    for (int i = 0; i < 2; i++) {
        int idx = tid + i * 256, k = idx >> 4, c = idx & 15;
        br0[i] = *(const float4*)&Bb[(size_t)k * N + c * 8];
        br1[i] = *(const float4*)&Bb[(size_t)k * N + c * 8 + 4];
    }
    As4[0][a_slot(am, ac)] = pack8(ar0, ar1);
#pragma unroll
    for (int i = 0; i < 2; i++) {
        int idx = tid + i * 256, k = idx >> 4, c = idx & 15;
        Bs4[0][b_slot(k, c)] = pack8(br0[i], br1[i]);
    }
    __syncthreads();

#pragma unroll
    for (int t = 0; t < GNT; t++) {
        const int cur = t & 1;
        if (t + 1 < GNT) {
            int kofs = (t + 1) * GBK;
#pragma unroll
            for (int i = 0; i < 2; i++) {
                int idx = tid + i * 256, k = idx >> 4, c = idx & 15;
                br0[i] = *(const float4*)&Bb[(size_t)(kofs + k) * N + c * 8];
                br1[i] = *(const float4*)&Bb[(size_t)(kofs + k) * N + c * 8 + 4];
            }
            ar0 = *(const float4*)&Ab[(size_t)am * KD + kofs + ac * 8];
            ar1 = *(const float4*)&Ab[(size_t)am * KD + kofs + ac * 8 + 4];
        }

        GEMM_COMPUTE_F16(asbase[cur], bsbase[cur]);

        if (t + 1 < GNT) {
            const int nxt = cur ^ 1;
#pragma unroll
            for (int i = 0; i < 2; i++) {
                int idx = tid + i * 256, k = idx >> 4, c = idx & 15;
                Bs4[nxt][b_slot(k, c)] = pack8(br0[i], br1[i]);
            }
            As4[nxt][a_slot(am, ac)] = pack8(ar0, ar1);
            __syncthreads();
        }
    }

#pragma unroll
    for (int mi = 0; mi < 2; mi++) {
        int m = m0 + wm * 32 + mi * 16 + g;
#pragma unroll
        for (int ni = 0; ni < 4; ni++) {
            int n = n0 + wn * 32 + ni * 8 + tig * 2;
            *(__half2*)&Cb[(size_t)m * N + n] =
                __floats2half2_rn(acc[mi][ni][0], acc[mi][ni][1]);
            *(__half2*)&Cb[(size_t)(m + 8) * N + n] =
                __floats2half2_rn(acc[mi][ni][2], acc[mi][ni][3]);
        }
    }
}

// ---------------------------------------------------------------------------
// GEMM 2: A fp32 (batched), B fp16 (batched), C fp32.
// ---------------------------------------------------------------------------
__global__ __launch_bounds__(256) void gemm_h_f32c_kernel(
    const float* __restrict__ A, const __half* __restrict__ Bm, float* __restrict__ Cm,
    int M, int N, size_t astride, size_t bstride)
{
    __shared__ __align__(16) __half As[2][GBM * GBK];
    __shared__ __align__(16) __half Bs[2][GBK * GBN];

    const int tid  = threadIdx.x;
    const int lane = tid & 31, wid = tid >> 5;
    const int wm = wid & 1, wn = wid >> 1;
    const int g = lane >> 2, tig = lane & 3;
    const int a_sel = lane & 15, a_hi = lane >> 4;
    const int b_koff = lane & 15, b_nsel = lane >> 4;

    const int m0 = blockIdx.y * GBM, n0 = blockIdx.x * GBN;
    const float*  Ab = A + astride * blockIdx.z + (size_t)m0 * KD;
    const __half* Bb = Bm + bstride * blockIdx.z + n0;
    float*        Cb = Cm + (size_t)blockIdx.z * M * N;

    unsigned asbase[2] = { (unsigned)__cvta_generic_to_shared(As[0]),
                           (unsigned)__cvta_generic_to_shared(As[1]) };
    unsigned bsbase[2] = { (unsigned)__cvta_generic_to_shared(Bs[0]),
                           (unsigned)__cvta_generic_to_shared(Bs[1]) };
    uint4* As4[2] = { (uint4*)As[0], (uint4*)As[1] };
    uint4* Bs4[2] = { (uint4*)Bs[0], (uint4*)Bs[1] };

    float acc[2][4][4];
#pragma unroll
    for (int mi = 0; mi < 2; mi++)
#pragma unroll
        for (int ni = 0; ni < 4; ni++)
#pragma unroll
            for (int j = 0; j < 4; j++) acc[mi][ni][j] = 0.f;

    const int am = tid >> 2, ac = tid & 3;
    float4 ar0, ar1;
    uint4  hreg[2];

    ar0 = *(const float4*)&Ab[(size_t)am * KD + ac * 8];
    ar1 = *(const float4*)&Ab[(size_t)am * KD + ac * 8 + 4];
#pragma unroll
    for (int i = 0; i < 2; i++) {
        int idx = tid + i * 256, k = idx >> 4, c = idx & 15;
        hreg[i] = *(const uint4*)(const void*)&Bb[(size_t)k * N + c * 8];
    }
    As4[0][a_slot(am, ac)] = pack8(ar0, ar1);
#pragma unroll
    for (int i = 0; i < 2; i++) {
        int idx = tid + i * 256, k = idx >> 4, c = idx & 15;
        Bs4[0][b_slot(k, c)] = hreg[i];
    }
    __syncthreads();

#pragma unroll
    for (int t = 0; t < GNT; t++) {
        const int cur = t & 1;
        if (t + 1 < GNT) {
            int kofs = (t + 1) * GBK;
#pragma unroll
            for (int i = 0; i < 2; i++) {
                int idx = tid + i * 256, k = idx >> 4, c = idx & 15;
                hreg[i] = *(const uint4*)(const void*)&Bb[(size_t)(kofs + k) * N + c * 8];
            }
            ar0 = *(const float4*)&Ab[(size_t)am * KD + kofs + ac * 8];
            ar1 = *(const float4*)&Ab[(size_t)am * KD + kofs + ac * 8 + 4];
        }

        GEMM_COMPUTE_F16(asbase[cur], bsbase[cur]);

        if (t + 1 < GNT) {
            const int nxt = cur ^ 1;
#pragma unroll
            for (int i = 0; i < 2; i++) {
                int idx = tid + i * 256, k = idx >> 4, c = idx & 15;
                Bs4[nxt][b_slot(k, c)] = hreg[i];
            }
            As4[nxt][a_slot(am, ac)] = pack8(ar0, ar1);
            __syncthreads();
        }
    }

#pragma unroll
    for (int mi = 0; mi < 2; mi++) {
        int m = m0 + wm * 32 + mi * 16 + g;
#pragma unroll
        for (int ni = 0; ni < 4; ni++) {
            int n = n0 + wn * 32 + ni * 8 + tig * 2;
            *(float2*)&Cb[(size_t)m * N + n] =
                make_float2(acc[mi][ni][0], acc[mi][ni][1]);
            *(float2*)&Cb[(size_t)(m + 8) * N + n] =
                make_float2(acc[mi][ni][2], acc[mi][ni][3]);
        }
    }
}

// ---------------------------------------------------------------------------
// Depthwise 3x3 (fp16 in/out, fp32 math). 16 output rows per block.
// ---------------------------------------------------------------------------
#define DWR 16
__global__ __launch_bounds__(256) void dw_kernel(
    const __half* __restrict__ in, __half* __restrict__ out, const float* __restrict__ wdw)
{
    const int band = blockIdx.x;
    const int bc   = blockIdx.y;
    const int ch   = bc % C3;
    const int tid  = threadIdx.x;
    const int y0   = band * DWR;

    __shared__ float s[DWR + 2][WW + 4];
    const __half* base = in + (size_t)bc * HW;

    for (int i = tid; i < (DWR + 2) * 16; i += 256) {
        int r = i >> 4, c8 = i & 15;
        int yy = y0 - 1 + r;
        float* d = &s[r][c8 * 8 + 1];
        if (yy >= 0 && yy < HH) {
            float4 rv = *(const float4*)(const void*)&base[yy * WW + c8 * 8];
            __half2 h0 = *(__half2*)&rv.x, h1 = *(__half2*)&rv.y;
            __half2 h2 = *(__half2*)&rv.z, h3 = *(__half2*)&rv.w;
            d[0] = __low2float(h0); d[1] = __high2float(h0);
            d[2] = __low2float(h1); d[3] = __high2float(h1);
            d[4] = __low2float(h2); d[5] = __high2float(h2);
            d[6] = __low2float(h3); d[7] = __high2float(h3);
        } else {
#pragma unroll
            for (int j = 0; j < 8; j++) d[j] = 0.f;
        }
    }
    if (tid < DWR + 2) { s[tid][0] = 0.f; s[tid][WW + 1] = 0.f; }

    float w[9];
#pragma unroll
    for (int i = 0; i < 9; i++) w[i] = __ldg(&wdw[ch * 9 + i]);
    __syncthreads();

    const int lane = tid & 31;
    for (int r = tid >> 5; r < DWR; r += 8) {
        __half* orow = out + (size_t)bc * HW + (y0 + r) * WW;
#pragma unroll
        for (int j = 0; j < 4; j++) {
            int cc = lane + j * 32;
            float acc = 0.f;
#pragma unroll
            for (int dy = 0; dy < 3; dy++)
#pragma unroll
                for (int dx = 0; dx < 3; dx++)
                    acc += w[dy * 3 + dx] * s[r + dy][cc + dx];
            orow[cc] = __float2half_rn(acc);
        }
    }
}

// ---------------------------------------------------------------------------
// Score partials (fp16 input, fp32 math).
// ---------------------------------------------------------------------------
__global__ __launch_bounds__(256) void score_partial_kernel(const __half* __restrict__ qkvd)
{
    int split = blockIdx.x;
    int unit  = blockIdx.y;
    int b = unit >> 2, hd = unit & 3;
    const __half* qb = qkvd + ((size_t)b * C3 + hd * CH) * HW;
    const __half* kb = qb + (size_t)C * HW;

    const int CS = 32;
    __shared__ float qs[CH][CS + 1], ks[CH][CS + 1];

    int tid = threadIdx.x, tx = tid & 15, ty = tid >> 4;
    float acc[3][3] = {{0.f,0.f,0.f},{0.f,0.f,0.f},{0.f,0.f,0.f}};
    float nacc = 0.f;

    int s_beg = split * (HW / SPLIT);
    int s_end = s_beg + (HW / SPLIT);
    for (int s0 = s_beg; s0 < s_end; s0 += CS) {
#pragma unroll
        for (int i = 0; i < (CH * CS) / 256; i++) {
            int idx = tid + i * 256;
            int r = idx >> 5, c = idx & 31;
            qs[r][c] = __half2float(qb[(size_t)r * HW + s0 + c]);
            ks[r][c] = __half2float(kb[(size_t)r * HW + s0 + c]);
        }
        __syncthreads();

        if (tid < 2 * CH) {
            int r = (tid < CH) ? tid : (tid - CH);
            const float* row = (tid < CH) ? qs[r] : ks[r];
#pragma unroll
            for (int j = 0; j < CS; j++) { float v = row[j]; nacc += v * v; }
        }

#pragma unroll 4
        for (int j = 0; j < CS; j++) {
            float q0 = qs[3 * ty + 0][j], q1 = qs[3 * ty + 1][j], q2 = qs[3 * ty + 2][j];
            float k0 = ks[3 * tx + 0][j], k1 = ks[3 * tx + 1][j], k2 = ks[3 * tx + 2][j];
            acc[0][0] += q0 * k0; acc[0][1] += q0 * k1; acc[0][2] += q0 * k2;
            acc[1][0] += q1 * k0; acc[1][1] += q1 * k1; acc[1][2] += q1 * k2;
            acc[2][0] += q2 * k0; acc[2][1] += q2 * k1; acc[2][2] += q2 * k2;
        }
        __syncthreads();
    }

    float* part = g_part + ((size_t)split * NB * NH + unit) * PART_STRIDE;
#pragma unroll
    for (int i = 0; i < 3; i++)
#pragma unroll
        for (int j = 0; j < 3; j++)
            part[(3 * ty + i) * CH + (3 * tx + j)] = acc[i][j];
    if (tid < 2 * CH) part[CH * CH + tid] = nacc;
}

// ---------------------------------------------------------------------------
__global__ __launch_bounds__(256) void softmax_kernel(const float* __restrict__ temperature)
{
    int unit = blockIdx.x;
    int hd = unit & 3;
    __shared__ float S[CH][CH];
    __shared__ float rq[CH], rk[CH];
    int tid = threadIdx.x;

    for (int e = tid; e < CH * CH; e += 256) {
        float s = 0.f;
#pragma unroll
        for (int p = 0; p < SPLIT; p++)
            s += g_part[((size_t)p * NB * NH + unit) * PART_STRIDE + e];
        S[e / CH][e % CH] = s;
    }
    if (tid < 2 * CH) {
        float s = 0.f;
#pragma unroll
        for (int p = 0; p < SPLIT; p++)
            s += g_part[((size_t)p * NB * NH + unit) * PART_STRIDE + CH * CH + tid];
        float inv = 1.f / fmaxf(sqrtf(s), 1e-12f);
        if (tid < CH) rq[tid] = inv; else rk[tid - CH] = inv;
    }
    __syncthreads();

    float temp = temperature[hd];
    if (tid < CH) {
        int i = tid;
        float row[CH];
        float mx = -3.402823466e38f;
#pragma unroll
        for (int j = 0; j < CH; j++) {
            float v = S[i][j] * rq[i] * rk[j] * temp;
            row[j] = v;
            mx = fmaxf(mx, v);
        }
        float sum = 0.f;
#pragma unroll
        for (int j = 0; j < CH; j++) { row[j] = expf(row[j] - mx); sum += row[j]; }
        float inv = 1.f / sum;
#pragma unroll
        for (int j = 0; j < CH; j++)
            g_score[(size_t)unit * CH * CH + i * CH + j] = row[j] * inv;
    }
}

// ---------------------------------------------------------------------------
__global__ __launch_bounds__(256) void pmat_kernel(const float* __restrict__ wproj)
{
    int unit = blockIdx.x;
    int b = unit >> 2, hd = unit & 3;
    __shared__ float sc[CH][CH];
    __shared__ float wp[C][CH];
    int tid = threadIdx.x;

    for (int e = tid; e < CH * CH; e += 256)
        sc[e / CH][e % CH] = g_score[(size_t)unit * CH * CH + e];
    for (int e = tid; e < C * CH; e += 256) {
        int o = e / CH, c = e % CH;
        wp[o][c] = wproj[o * C + hd * CH + c];
    }
    __syncthreads();

    for (int e = tid; e < C * CH; e += 256) {
        int o = e / CH, d = e % CH;
        float acc = 0.f;
#pragma unroll
        for (int c = 0; c < CH; c++) acc += wp[o][c] * sc[c][d];
        g_P[((size_t)b * C + o) * C + hd * CH + d] = acc;
    }
}

// ---------------------------------------------------------------------------
extern "C" void kernel_launch(void* const* d_in, const int* in_sizes, int n_in,
                              void* d_out, int out_size)
{
    (void)in_sizes; (void)n_in; (void)out_size;
    const float* x      = (const float*)d_in[0];
    const float* w_qkv  = (const float*)d_in[1];
    const float* w_dw   = (const float*)d_in[2];
    const float* w_proj = (const float*)d_in[3];
    const float* temp   = (const float*)d_in[4];
    float* out = (float*)d_out;

    __half *qkv, *dwb;
    float *pmat;
    cudaGetSymbolAddress((void**)&qkv,  g_qkv);
    cudaGetSymbolAddress((void**)&dwb,  g_dw);
    cudaGetSymbolAddress((void**)&pmat, g_P);

    // 1) qkv = W_qkv (576x192) * x[b] (192x16384)  — fp16 MMA, fp16 output
    gemm_f32b_h_kernel<<<dim3(HW / GBN, C3 / GBM, NB), 256>>>(
        w_qkv, x, qkv, C3, HW, (size_t)KD * HW);
    // 2) depthwise 3x3 (fp16 -> fp16)
    dw_kernel<<<dim3(HH / DWR, NB * C3), 256>>>(qkv, dwb, w_dw);
    // 3) split-K score partials
    score_partial_kernel<<<dim3(SPLIT, NB * NH), 256>>>(dwb);
    // 4) normalize + temperature + softmax
    softmax_kernel<<<NB * NH, 256>>>(temp);
    // 5) P_b = W_proj @ blockdiag(score_b)
    pmat_kernel<<<NB * NH, 256>>>(w_proj);
    // 6) out = P_b (192x192) * v[b] (192x16384)  — fp16 MMA, fp32 output
    gemm_h_f32c_kernel<<<dim3(HW / GBN, C / GBM, NB), 256>>>(
        pmat, dwb + (size_t)2 * C * HW, out, C, HW,
        (size_t)C * C, (size_t)C3 * HW);
}

// round 9
// speedup vs baseline: 1.8396x; 1.1493x over previous
#include <cuda_runtime.h>
#include <cuda_fp16.h>
#include <math.h>

#define NB 8
#define C 192
#define C3 576
#define NH 4
#define CH 48
#define HH 128
#define WW 128
#define HW 16384
#define SPLIT 32
#define PART_STRIDE (CH*CH + 2*CH)   /* 2400 */

// Scratch (device globals: no allocation allowed in kernel_launch)
__device__ __half g_qkv[NB*C3*HW];                 // 151 MB
__device__ __half g_dw [NB*C3*HW];                 // 151 MB
__device__ float g_part[SPLIT*NB*NH*PART_STRIDE];
__device__ float g_score[NB*NH*CH*CH];
__device__ float g_P   [NB*C*C];

// ===========================================================================
// FP16 tensor-core GEMM (m16n8k16, fp32 accum).
// BM=64, BN=128, BK=32, 256 threads (8 warps 2x4), warp tile 32x32.
// ===========================================================================
#define GBM 64
#define GBN 128
#define GBK 32
#define KD  192
#define GNT (KD/GBK)   /* 6 */

__device__ __forceinline__ unsigned h2u(__half2 h) {
    return *(unsigned*)&h;
}
__device__ __forceinline__ void ldsm_x4(unsigned& r0, unsigned& r1, unsigned& r2,
                                        unsigned& r3, unsigned addr) {
    asm volatile("ldmatrix.sync.aligned.m8n8.x4.shared.b16 {%0,%1,%2,%3}, [%4];"
        : "=r"(r0), "=r"(r1), "=r"(r2), "=r"(r3) : "r"(addr));
}
__device__ __forceinline__ void ldsm_x4_t(unsigned& r0, unsigned& r1, unsigned& r2,
                                          unsigned& r3, unsigned addr) {
    asm volatile("ldmatrix.sync.aligned.m8n8.x4.trans.shared.b16 {%0,%1,%2,%3}, [%4];"
        : "=r"(r0), "=r"(r1), "=r"(r2), "=r"(r3) : "r"(addr));
}

#define MMA_F16(d, av, bv)                                                    \
  asm("mma.sync.aligned.m16n8k16.row.col.f32.f16.f16.f32 "                    \
      "{%0,%1,%2,%3}, {%4,%5,%6,%7}, {%8,%9}, {%0,%1,%2,%3};"                 \
      : "+f"(d[0]), "+f"(d[1]), "+f"(d[2]), "+f"(d[3])                        \
      : "r"(av[0]), "r"(av[1]), "r"(av[2]), "r"(av[3]),                       \
        "r"(bv[0]), "r"(bv[1]))

// A smem chunk slot (uint4 index) for logical (m, chunk c in 0..3)
__device__ __forceinline__ int a_slot(int m, int c) {
    return (m >> 1) * 8 + ((((m & 1) << 2) + c) ^ ((m >> 1) & 7));
}
// B smem chunk slot for logical (k, chunk c in 0..15)
__device__ __forceinline__ int b_slot(int k, int c) {
    return k * 16 + (c ^ (k & 7));
}

#define GEMM_COMPUTE_F16(asbase_, bsbase_)                                    \
  do {                                                                        \
    _Pragma("unroll")                                                         \
    for (int kk = 0; kk < 2; kk++) {                                          \
        unsigned a[2][4], b[4][2];                                            \
        _Pragma("unroll")                                                     \
        for (int mi = 0; mi < 2; mi++) {                                      \
            int m = wm * 32 + mi * 16 + a_sel;                                \
            int c = 2 * kk + a_hi;                                            \
            ldsm_x4(a[mi][0], a[mi][1], a[mi][2], a[mi][3],                   \
                    (asbase_) + a_slot(m, c) * 16);                           \
        }                                                                     \
        _Pragma("unroll")                                                     \
        for (int np = 0; np < 2; np++) {                                      \
            int k = kk * 16 + b_koff;                                         \
            int cb = wn * 4 + 2 * np + b_nsel;                                \
            ldsm_x4_t(b[2*np][0], b[2*np][1], b[2*np+1][0], b[2*np+1][1],     \
                      (bsbase_) + b_slot(k, cb) * 16);                        \
        }                                                                     \
        _Pragma("unroll")                                                     \
        for (int mi = 0; mi < 2; mi++)                                        \
            _Pragma("unroll")                                                 \
            for (int ni = 0; ni < 4; ni++)                                    \
                MMA_F16(acc[mi][ni], a[mi], b[ni]);                           \
    }                                                                         \
  } while (0)

__device__ __forceinline__ uint4 pack8(float4 f0, float4 f1) {
    uint4 v;
    v.x = h2u(__floats2half2_rn(f0.x, f0.y));
    v.y = h2u(__floats2half2_rn(f0.z, f0.w));
    v.z = h2u(__floats2half2_rn(f1.x, f1.y));
    v.w = h2u(__floats2half2_rn(f1.z, f1.w));
    return v;
}

// ---------------------------------------------------------------------------
// GEMM 1: A fp32 (shared weights), B fp32 (batched), C fp16.
// ---------------------------------------------------------------------------
__global__ __launch_bounds__(256) void gemm_f32b_h_kernel(
    const float* __restrict__ A, const float* __restrict__ Bm, __half* __restrict__ Cm,
    int M, int N, size_t bstride)
{
    __shared__ __align__(16) __half As[2][GBM * GBK];
    __shared__ __align__(16) __half Bs[2][GBK * GBN];

    const int tid  = threadIdx.x;
    const int lane = tid & 31, wid = tid >> 5;
    const int wm = wid & 1, wn = wid >> 1;
    const int g = lane >> 2, tig = lane & 3;
    const int a_sel = lane & 15, a_hi = lane >> 4;
    const int b_koff = lane & 15, b_nsel = lane >> 4;

    const int m0 = blockIdx.y * GBM, n0 = blockIdx.x * GBN;
    const float* Ab = A + (size_t)m0 * KD;
    const float* Bb = Bm + bstride * blockIdx.z + n0;
    __half*      Cb = Cm + (size_t)blockIdx.z * M * N;

    unsigned asbase[2] = { (unsigned)__cvta_generic_to_shared(As[0]),
                           (unsigned)__cvta_generic_to_shared(As[1]) };
    unsigned bsbase[2] = { (unsigned)__cvta_generic_to_shared(Bs[0]),
                           (unsigned)__cvta_generic_to_shared(Bs[1]) };
    uint4* As4[2] = { (uint4*)As[0], (uint4*)As[1] };
    uint4* Bs4[2] = { (uint4*)Bs[0], (uint4*)Bs[1] };

    float acc[2][4][4];
#pragma unroll
    for (int mi = 0; mi < 2; mi++)
#pragma unroll
        for (int ni = 0; ni < 4; ni++)
#pragma unroll
            for (int j = 0; j < 4; j++) acc[mi][ni][j] = 0.f;

    const int am = tid >> 2, ac = tid & 3;
    float4 ar0, ar1, br0[2], br1[2];

    ar0 = *(const float4*)&Ab[(size_t)am * KD + ac * 8];
    ar1 = *(const float4*)&Ab[(size_t)am * KD + ac * 8 + 4];
#pragma unroll
    for (int i = 0; i < 2; i++) {
        int idx = tid + i * 256, k = idx >> 4, c = idx & 15;
        br0[i] = *(const float4*)&Bb[(size_t)k * N + c * 8];
        br1[i] = *(const float4*)&Bb[(size_t)k * N + c * 8 + 4];
    }
    As4[0][a_slot(am, ac)] = pack8(ar0, ar1);
#pragma unroll
    for (int i = 0; i < 2; i++) {
        int idx = tid + i * 256, k = idx >> 4, c = idx & 15;
        Bs4[0][b_slot(k, c)] = pack8(br0[i], br1[i]);
    }
    __syncthreads();

#pragma unroll
    for (int t = 0; t < GNT; t++) {
        const int cur = t & 1;
        if (t + 1 < GNT) {
            int kofs = (t + 1) * GBK;
#pragma unroll
            for (int i = 0; i < 2; i++) {
                int idx = tid + i * 256, k = idx >> 4, c = idx & 15;
                br0[i] = *(const float4*)&Bb[(size_t)(kofs + k) * N + c * 8];
                br1[i] = *(const float4*)&Bb[(size_t)(kofs + k) * N + c * 8 + 4];
            }
            ar0 = *(const float4*)&Ab[(size_t)am * KD + kofs + ac * 8];
            ar1 = *(const float4*)&Ab[(size_t)am * KD + kofs + ac * 8 + 4];
        }

        GEMM_COMPUTE_F16(asbase[cur], bsbase[cur]);

        if (t + 1 < GNT) {
            const int nxt = cur ^ 1;
#pragma unroll
            for (int i = 0; i < 2; i++) {
                int idx = tid + i * 256, k = idx >> 4, c = idx & 15;
                Bs4[nxt][b_slot(k, c)] = pack8(br0[i], br1[i]);
            }
            As4[nxt][a_slot(am, ac)] = pack8(ar0, ar1);
            __syncthreads();
        }
    }

#pragma unroll
    for (int mi = 0; mi < 2; mi++) {
        int m = m0 + wm * 32 + mi * 16 + g;
#pragma unroll
        for (int ni = 0; ni < 4; ni++) {
            int n = n0 + wn * 32 + ni * 8 + tig * 2;
            *(__half2*)&Cb[(size_t)m * N + n] =
                __floats2half2_rn(acc[mi][ni][0], acc[mi][ni][1]);
            *(__half2*)&Cb[(size_t)(m + 8) * N + n] =
                __floats2half2_rn(acc[mi][ni][2], acc[mi][ni][3]);
        }
    }
}

// ---------------------------------------------------------------------------
// GEMM 2: A fp32 (batched), B fp16 (batched), C fp32.
// ---------------------------------------------------------------------------
__global__ __launch_bounds__(256) void gemm_h_f32c_kernel(
    const float* __restrict__ A, const __half* __restrict__ Bm, float* __restrict__ Cm,
    int M, int N, size_t astride, size_t bstride)
{
    __shared__ __align__(16) __half As[2][GBM * GBK];
    __shared__ __align__(16) __half Bs[2][GBK * GBN];

    const int tid  = threadIdx.x;
    const int lane = tid & 31, wid = tid >> 5;
    const int wm = wid & 1, wn = wid >> 1;
    const int g = lane >> 2, tig = lane & 3;
    const int a_sel = lane & 15, a_hi = lane >> 4;
    const int b_koff = lane & 15, b_nsel = lane >> 4;

    const int m0 = blockIdx.y * GBM, n0 = blockIdx.x * GBN;
    const float*  Ab = A + astride * blockIdx.z + (size_t)m0 * KD;
    const __half* Bb = Bm + bstride * blockIdx.z + n0;
    float*        Cb = Cm + (size_t)blockIdx.z * M * N;

    unsigned asbase[2] = { (unsigned)__cvta_generic_to_shared(As[0]),
                           (unsigned)__cvta_generic_to_shared(As[1]) };
    unsigned bsbase[2] = { (unsigned)__cvta_generic_to_shared(Bs[0]),
                           (unsigned)__cvta_generic_to_shared(Bs[1]) };
    uint4* As4[2] = { (uint4*)As[0], (uint4*)As[1] };
    uint4* Bs4[2] = { (uint4*)Bs[0], (uint4*)Bs[1] };

    float acc[2][4][4];
#pragma unroll
    for (int mi = 0; mi < 2; mi++)
#pragma unroll
        for (int ni = 0; ni < 4; ni++)
#pragma unroll
            for (int j = 0; j < 4; j++) acc[mi][ni][j] = 0.f;

    const int am = tid >> 2, ac = tid & 3;
    float4 ar0, ar1;
    uint4  hreg[2];

    ar0 = *(const float4*)&Ab[(size_t)am * KD + ac * 8];
    ar1 = *(const float4*)&Ab[(size_t)am * KD + ac * 8 + 4];
#pragma unroll
    for (int i = 0; i < 2; i++) {
        int idx = tid + i * 256, k = idx >> 4, c = idx & 15;
        hreg[i] = *(const uint4*)(const void*)&Bb[(size_t)k * N + c * 8];
    }
    As4[0][a_slot(am, ac)] = pack8(ar0, ar1);
#pragma unroll
    for (int i = 0; i < 2; i++) {
        int idx = tid + i * 256, k = idx >> 4, c = idx & 15;
        Bs4[0][b_slot(k, c)] = hreg[i];
    }
    __syncthreads();

#pragma unroll
    for (int t = 0; t < GNT; t++) {
        const int cur = t & 1;
        if (t + 1 < GNT) {
            int kofs = (t + 1) * GBK;
#pragma unroll
            for (int i = 0; i < 2; i++) {
                int idx = tid + i * 256, k = idx >> 4, c = idx & 15;
                hreg[i] = *(const uint4*)(const void*)&Bb[(size_t)(kofs + k) * N + c * 8];
            }
            ar0 = *(const float4*)&Ab[(size_t)am * KD + kofs + ac * 8];
            ar1 = *(const float4*)&Ab[(size_t)am * KD + kofs + ac * 8 + 4];
        }

        GEMM_COMPUTE_F16(asbase[cur], bsbase[cur]);

        if (t + 1 < GNT) {
            const int nxt = cur ^ 1;
#pragma unroll
            for (int i = 0; i < 2; i++) {
                int idx = tid + i * 256, k = idx >> 4, c = idx & 15;
                Bs4[nxt][b_slot(k, c)] = hreg[i];
            }
            As4[nxt][a_slot(am, ac)] = pack8(ar0, ar1);
            __syncthreads();
        }
    }

#pragma unroll
    for (int mi = 0; mi < 2; mi++) {
        int m = m0 + wm * 32 + mi * 16 + g;
#pragma unroll
        for (int ni = 0; ni < 4; ni++) {
            int n = n0 + wn * 32 + ni * 8 + tig * 2;
            *(float2*)&Cb[(size_t)m * N + n] =
                make_float2(acc[mi][ni][0], acc[mi][ni][1]);
            *(float2*)&Cb[(size_t)(m + 8) * N + n] =
                make_float2(acc[mi][ni][2], acc[mi][ni][3]);
        }
    }
}

// ---------------------------------------------------------------------------
// Depthwise 3x3 (fp16 in/out, fp32 math). 16 output rows per block.
// Aligned smem layout (data at col offset 4) -> vectorized STS.128.
// ---------------------------------------------------------------------------
#define DWR 16
__global__ __launch_bounds__(256) void dw_kernel(
    const __half* __restrict__ in, __half* __restrict__ out, const float* __restrict__ wdw)
{
    const int band = blockIdx.x;
    const int bc   = blockIdx.y;
    const int ch   = bc % C3;
    const int tid  = threadIdx.x;
    const int y0   = band * DWR;

    __shared__ float s[DWR + 2][WW + 12];   // data cols 4..131; halo at 3, 132
    const __half* base = in + (size_t)bc * HW;

    for (int i = tid; i < (DWR + 2) * 16; i += 256) {
        int r = i >> 4, c8 = i & 15;
        int yy = y0 - 1 + r;
        float4 v0 = make_float4(0.f, 0.f, 0.f, 0.f);
        float4 v1 = v0;
        if (yy >= 0 && yy < HH) {
            uint4 rv = *(const uint4*)(const void*)&base[yy * WW + c8 * 8];
            float2 f0 = __half22float2(*(__half2*)&rv.x);
            float2 f1 = __half22float2(*(__half2*)&rv.y);
            float2 f2 = __half22float2(*(__half2*)&rv.z);
            float2 f3 = __half22float2(*(__half2*)&rv.w);
            v0 = make_float4(f0.x, f0.y, f1.x, f1.y);
            v1 = make_float4(f2.x, f2.y, f3.x, f3.y);
        }
        *(float4*)&s[r][c8 * 8 + 4] = v0;
        *(float4*)&s[r][c8 * 8 + 8] = v1;
    }
    if (tid < DWR + 2) { s[tid][3] = 0.f; s[tid][WW + 4] = 0.f; }

    float w[9];
#pragma unroll
    for (int i = 0; i < 9; i++) w[i] = __ldg(&wdw[ch * 9 + i]);
    __syncthreads();

    const int lane = tid & 31;
    for (int r = tid >> 5; r < DWR; r += 8) {
        __half* orow = out + (size_t)bc * HW + (y0 + r) * WW;
#pragma unroll
        for (int j = 0; j < 4; j++) {
            int cc = lane + j * 32;
            float acc = 0.f;
#pragma unroll
            for (int dy = 0; dy < 3; dy++)
#pragma unroll
                for (int dx = 0; dx < 3; dx++)
                    acc += w[dy * 3 + dx] * s[r + dy][cc + 3 + dx];
            orow[cc] = __float2half_rn(acc);
        }
    }
}

// ---------------------------------------------------------------------------
// Score partials via fp16 MMA: per (split, unit), S = Q.K^T over 512 spatial,
// Q,K [48 x 512] fp16. 4 iters of [48 x 128] tiles; warp w owns spatial k16
// slice (chunks 2w, 2w+1); cross-warp reduce via smem atomics.
// Plus per-row sum-of-squares on a 192-thread sideband.
// ---------------------------------------------------------------------------
__device__ __forceinline__ int sc_slot(int r, int c) {  // [48 rows][16 chunks]
    return r * 16 + (c ^ (r & 7));
}

__global__ __launch_bounds__(256) void score_mma_kernel(const __half* __restrict__ qkvd)
{
    const int split = blockIdx.x;
    const int unit  = blockIdx.y;
    const int b = unit >> 2, hd = unit & 3;
    const __half* qb = qkvd + ((size_t)b * C3 + hd * CH) * HW;
    const __half* kb = qb + (size_t)C * HW;

    __shared__ __align__(16) uint4 Qs[CH * 16];
    __shared__ __align__(16) uint4 Ks[CH * 16];
    __shared__ float S[CH][CH];
    __shared__ float sqbuf[192];

    const int tid = threadIdx.x, lane = tid & 31, wid = tid >> 5;
    const unsigned qbase = (unsigned)__cvta_generic_to_shared(Qs);
    const unsigned kbase = (unsigned)__cvta_generic_to_shared(Ks);

    for (int e = tid; e < CH * CH; e += 256) S[e / CH][e % CH] = 0.f;

    float acc[3][6][4];
#pragma unroll
    for (int mi = 0; mi < 3; mi++)
#pragma unroll
        for (int ni = 0; ni < 6; ni++)
#pragma unroll
            for (int j = 0; j < 4; j++) acc[mi][ni][j] = 0.f;
    float sq = 0.f;

    const int c0 = 2 * wid;                       // warp's spatial chunk pair
    const int ra = lane & 15;                     // A ldsm row offset
    const int ca = lane >> 4;                     // A ldsm chunk offset
    const int rb = (lane & 7) + ((lane >> 4) << 3);
    const int cbo = (lane >> 3) & 1;

#pragma unroll
    for (int it = 0; it < 4; it++) {
        const int s0 = split * 512 + it * 128;
        __syncthreads();
#pragma unroll
        for (int i = 0; i < 3; i++) {             // 768 chunks / 256 threads
            int idx = tid + i * 256, r = idx >> 4, c = idx & 15;
            Qs[sc_slot(r, c)] = *(const uint4*)(const void*)&qb[(size_t)r * HW + s0 + c * 8];
            Ks[sc_slot(r, c)] = *(const uint4*)(const void*)&kb[(size_t)r * HW + s0 + c * 8];
        }
        __syncthreads();

        // sum-of-squares sideband: thread t<192 owns (row = t/2, half = t&1)
        if (tid < 192) {
            int row = tid >> 1, hf = tid & 1;
            const uint4* src = (row < CH) ? Qs : Ks;
            int r = (row < CH) ? row : row - CH;
#pragma unroll
            for (int j = 0; j < 8; j++) {
                int c = hf * 8 + j;
                uint4 v = src[sc_slot(r, c)];
                float2 f0 = __half22float2(*(__half2*)&v.x);
                float2 f1 = __half22float2(*(__half2*)&v.y);
                float2 f2 = __half22float2(*(__half2*)&v.z);
                float2 f3 = __half22float2(*(__half2*)&v.w);
                sq += f0.x*f0.x + f0.y*f0.y + f1.x*f1.x + f1.y*f1.y
                    + f2.x*f2.x + f2.y*f2.y + f3.x*f3.x + f3.y*f3.y;
            }
        }

        // MMA phase: warp handles spatial k16 = chunks c0, c0+1
        unsigned a[3][4];
#pragma unroll
        for (int mi = 0; mi < 3; mi++) {
            int r = 16 * mi + ra, c = c0 + ca;
            ldsm_x4(a[mi][0], a[mi][1], a[mi][2], a[mi][3],
                    qbase + (unsigned)(sc_slot(r, c) * 16));
        }
        unsigned bf[6][2];
#pragma unroll
        for (int nj = 0; nj < 3; nj++) {
            int r = 16 * nj + rb, c = c0 + cbo;
            ldsm_x4(bf[2*nj][0], bf[2*nj][1], bf[2*nj+1][0], bf[2*nj+1][1],
                    kbase + (unsigned)(sc_slot(r, c) * 16));
        }
#pragma unroll
        for (int mi = 0; mi < 3; mi++)
#pragma unroll
            for (int ni = 0; ni < 6; ni++)
                MMA_F16(acc[mi][ni], a[mi], bf[ni]);
    }

    __syncthreads();
    // cross-warp reduction into S
#pragma unroll
    for (int mi = 0; mi < 3; mi++)
#pragma unroll
        for (int ni = 0; ni < 6; ni++)
#pragma unroll
            for (int d = 0; d < 4; d++) {
                int m = 16 * mi + (lane >> 2) + 8 * (d >> 1);
                int n = 8 * ni + (lane & 3) * 2 + (d & 1);
                atomicAdd(&S[m][n], acc[mi][ni][d]);
            }
    if (tid < 192) sqbuf[tid] = sq;
    __syncthreads();

    float* part = g_part + ((size_t)split * NB * NH + unit) * PART_STRIDE;
    for (int e = tid; e < CH * CH; e += 256) part[e] = S[e / CH][e % CH];
    if (tid < 2 * CH) part[CH * CH + tid] = sqbuf[2 * tid] + sqbuf[2 * tid + 1];
}

// ---------------------------------------------------------------------------
__global__ __launch_bounds__(256) void softmax_kernel(const float* __restrict__ temperature)
{
    int unit = blockIdx.x;
    int hd = unit & 3;
    __shared__ float S[CH][CH];
    __shared__ float rq[CH], rk[CH];
    int tid = threadIdx.x;

    for (int e = tid; e < CH * CH; e += 256) {
        float s = 0.f;
#pragma unroll
        for (int p = 0; p < SPLIT; p++)
            s += g_part[((size_t)p * NB * NH + unit) * PART_STRIDE + e];
        S[e / CH][e % CH] = s;
    }
    if (tid < 2 * CH) {
        float s = 0.f;
#pragma unroll
        for (int p = 0; p < SPLIT; p++)
            s += g_part[((size_t)p * NB * NH + unit) * PART_STRIDE + CH * CH + tid];
        float inv = 1.f / fmaxf(sqrtf(s), 1e-12f);
        if (tid < CH) rq[tid] = inv; else rk[tid - CH] = inv;
    }
    __syncthreads();

    float temp = temperature[hd];
    if (tid < CH) {
        int i = tid;
        float row[CH];
        float mx = -3.402823466e38f;
#pragma unroll
        for (int j = 0; j < CH; j++) {
            float v = S[i][j] * rq[i] * rk[j] * temp;
            row[j] = v;
            mx = fmaxf(mx, v);
        }
        float sum = 0.f;
#pragma unroll
        for (int j = 0; j < CH; j++) { row[j] = expf(row[j] - mx); sum += row[j]; }
        float inv = 1.f / sum;
#pragma unroll
        for (int j = 0; j < CH; j++)
            g_score[(size_t)unit * CH * CH + i * CH + j] = row[j] * inv;
    }
}

// ---------------------------------------------------------------------------
__global__ __launch_bounds__(256) void pmat_kernel(const float* __restrict__ wproj)
{
    int unit = blockIdx.x;
    int b = unit >> 2, hd = unit & 3;
    __shared__ float sc[CH][CH];
    __shared__ float wp[C][CH];
    int tid = threadIdx.x;

    for (int e = tid; e < CH * CH; e += 256)
        sc[e / CH][e % CH] = g_score[(size_t)unit * CH * CH + e];
    for (int e = tid; e < C * CH; e += 256) {
        int o = e / CH, c = e % CH;
        wp[o][c] = wproj[o * C + hd * CH + c];
    }
    __syncthreads();

    for (int e = tid; e < C * CH; e += 256) {
        int o = e / CH, d = e % CH;
        float acc = 0.f;
#pragma unroll
        for (int c = 0; c < CH; c++) acc += wp[o][c] * sc[c][d];
        g_P[((size_t)b * C + o) * C + hd * CH + d] = acc;
    }
}

// ---------------------------------------------------------------------------
extern "C" void kernel_launch(void* const* d_in, const int* in_sizes, int n_in,
                              void* d_out, int out_size)
{
    (void)in_sizes; (void)n_in; (void)out_size;
    const float* x      = (const float*)d_in[0];
    const float* w_qkv  = (const float*)d_in[1];
    const float* w_dw   = (const float*)d_in[2];
    const float* w_proj = (const float*)d_in[3];
    const float* temp   = (const float*)d_in[4];
    float* out = (float*)d_out;

    __half *qkv, *dwb;
    float *pmat;
    cudaGetSymbolAddress((void**)&qkv,  g_qkv);
    cudaGetSymbolAddress((void**)&dwb,  g_dw);
    cudaGetSymbolAddress((void**)&pmat, g_P);

    // 1) qkv = W_qkv (576x192) * x[b] (192x16384)  — fp16 MMA, fp16 output
    gemm_f32b_h_kernel<<<dim3(HW / GBN, C3 / GBM, NB), 256>>>(
        w_qkv, x, qkv, C3, HW, (size_t)KD * HW);
    // 2) depthwise 3x3 (fp16 -> fp16)
    dw_kernel<<<dim3(HH / DWR, NB * C3), 256>>>(qkv, dwb, w_dw);
    // 3) split-K score partials (fp16 MMA)
    score_mma_kernel<<<dim3(SPLIT, NB * NH), 256>>>(dwb);
    // 4) normalize + temperature + softmax
    softmax_kernel<<<NB * NH, 256>>>(temp);
    // 5) P_b = W_proj @ blockdiag(score_b)
    pmat_kernel<<<NB * NH, 256>>>(w_proj);
    // 6) out = P_b (192x192) * v[b] (192x16384)  — fp16 MMA, fp32 output
    gemm_h_f32c_kernel<<<dim3(HW / GBN, C / GBM, NB), 256>>>(
        pmat, dwb + (size_t)2 * C * HW, out, C, HW,
        (size_t)C * C, (size_t)C3 * HW);
}